// round 2
// baseline (speedup 1.0000x reference)
#include <cuda_runtime.h>

#define BATCH 8
#define NN 2048
#define IN_DIM 128
#define OUT_DIM 64
#define NEG_SLOPE 0.2f

// Scratch (allocation-free rule: __device__ globals)
__device__ float g_h[BATCH * NN * OUT_DIM];   // 4 MB
__device__ float g_fi[BATCH * NN];
__device__ float g_fj[BATCH * NN];

// ---- packed f32x2 helpers (ptxas never emits FFMA2 from C++) ----
__device__ __forceinline__ unsigned long long pack2(float x, float y) {
    unsigned long long r;
    asm("mov.b64 %0, {%1, %2};" : "=l"(r) : "f"(x), "f"(y));
    return r;
}
__device__ __forceinline__ void unpack2(unsigned long long v, float& x, float& y) {
    asm("mov.b64 {%0, %1}, %2;" : "=f"(x), "=f"(y) : "l"(v));
}
__device__ __forceinline__ void ffma2(unsigned long long& d, unsigned long long a, unsigned long long b) {
    asm("fma.rn.f32x2 %0, %1, %2, %0;" : "+l"(d) : "l"(a), "l"(b));
}

__device__ __forceinline__ float neg_inf_f() { return __int_as_float(0xff800000); }

// ============================================================================
// Kernel A: h = x @ W (fp32), f_i = h·a[:64], f_j = h·a[64:]
// One block = 32 rows, 256 threads, each thread: 1 row x 8 dims.
// ============================================================================
__global__ void __launch_bounds__(256) gat_h_kernel(
    const float* __restrict__ x, const float* __restrict__ W, const float* __restrict__ a)
{
    __shared__ float W_s[IN_DIM * OUT_DIM];  // 32 KB
    int tid = threadIdx.x;
    {
        const float4* Wv = (const float4*)W;
        float4* Wsv = (float4*)W_s;
#pragma unroll
        for (int i = 0; i < 8; i++) Wsv[tid + i * 256] = Wv[tid + i * 256];
    }
    __syncthreads();

    int r = tid >> 3;            // 0..31 row within block
    int dg = (tid & 7) * 8;      // dim group start
    int row = blockIdx.x * 32 + r;
    const float* xrow = x + (size_t)row * IN_DIM;

    float acc[8];
#pragma unroll
    for (int d = 0; d < 8; d++) acc[d] = 0.0f;

#pragma unroll 4
    for (int k = 0; k < IN_DIM; k++) {
        float xv = __ldg(&xrow[k]);            // broadcast among the 8 dim-group threads
        const float* wr = &W_s[k * OUT_DIM + dg];
#pragma unroll
        for (int d = 0; d < 8; d++) acc[d] = fmaf(xv, wr[d], acc[d]);
    }

    // write h (two float4 per thread, contiguous per warp)
    size_t hbase = (size_t)row * OUT_DIM + dg;
    *(float4*)&g_h[hbase]     = make_float4(acc[0], acc[1], acc[2], acc[3]);
    *(float4*)&g_h[hbase + 4] = make_float4(acc[4], acc[5], acc[6], acc[7]);

    // partial dots with a_i / a_j, reduce across the 8 threads of this row
    float fi = 0.0f, fj = 0.0f;
#pragma unroll
    for (int d = 0; d < 8; d++) {
        fi = fmaf(acc[d], __ldg(&a[dg + d]), fi);
        fj = fmaf(acc[d], __ldg(&a[OUT_DIM + dg + d]), fj);
    }
#pragma unroll
    for (int off = 4; off > 0; off >>= 1) {
        fi += __shfl_down_sync(0xffffffffu, fi, off);
        fj += __shfl_down_sync(0xffffffffu, fj, off);
    }
    if ((tid & 7) == 0) {
        g_fi[row] = fi;
        g_fj[row] = fj;
    }
}

// ============================================================================
// Kernel C: per (i-tile of 64 rows, batch): softmax stats (2 sweeps), then
// tiled alpha computation + write + out accumulation with f32x2 FFMA.
// Grid: (32, 8), 256 threads. Static SMEM ~42 KB.
// ============================================================================
__global__ void __launch_bounds__(256) gat_main_kernel(
    const float* __restrict__ adj, float* __restrict__ out, float* __restrict__ alpha_out)
{
    __shared__ float fj_s[NN];            // 8 KB
    __shared__ float fi_s[64];
    __shared__ float m_s[64];
    __shared__ float sinv_s[64];
    __shared__ float h_s[64 * OUT_DIM];   // 16 KB   (j-tile of h)
    __shared__ float alpha_t[64 * 65];    // 16.25 KB, stride-65 padded (transposed alpha tile)

    int tid  = threadIdx.x;
    int lane = tid & 31;
    int w    = tid >> 5;                  // 8 warps
    int b    = blockIdx.y;
    int i0   = blockIdx.x * 64;

    // load f_j (full batch row) and f_i tile
    for (int j = tid; j < NN; j += 256) fj_s[j] = g_fj[b * NN + j];
    if (tid < 64) fi_s[tid] = g_fi[b * NN + i0 + tid];
    __syncthreads();

    // ---- Pass 1: per-row masked max, then sum of exp (adj stays hot in L1) ----
#pragma unroll 1
    for (int rr = 0; rr < 8; rr++) {
        int r = w * 8 + rr;
        const float* adjrow = adj + (size_t)(i0 + r) * NN;
        float fi = fi_s[r];

        float m = neg_inf_f();
#pragma unroll 1
        for (int j = lane; j < NN; j += 128) {
            float a0 = adjrow[j];
            float a1 = adjrow[j + 32];
            float a2 = adjrow[j + 64];
            float a3 = adjrow[j + 96];
            float z0 = fi + fj_s[j];      z0 = fmaxf(z0, NEG_SLOPE * z0);
            float z1 = fi + fj_s[j + 32]; z1 = fmaxf(z1, NEG_SLOPE * z1);
            float z2 = fi + fj_s[j + 64]; z2 = fmaxf(z2, NEG_SLOPE * z2);
            float z3 = fi + fj_s[j + 96]; z3 = fmaxf(z3, NEG_SLOPE * z3);
            if (a0 != 0.0f) m = fmaxf(m, z0);
            if (a1 != 0.0f) m = fmaxf(m, z1);
            if (a2 != 0.0f) m = fmaxf(m, z2);
            if (a3 != 0.0f) m = fmaxf(m, z3);
        }
#pragma unroll
        for (int off = 16; off > 0; off >>= 1)
            m = fmaxf(m, __shfl_xor_sync(0xffffffffu, m, off));

        float s = 0.0f;
#pragma unroll 1
        for (int j = lane; j < NN; j += 128) {
            float a0 = adjrow[j];
            float a1 = adjrow[j + 32];
            float a2 = adjrow[j + 64];
            float a3 = adjrow[j + 96];
            float z0 = fi + fj_s[j];      z0 = fmaxf(z0, NEG_SLOPE * z0);
            float z1 = fi + fj_s[j + 32]; z1 = fmaxf(z1, NEG_SLOPE * z1);
            float z2 = fi + fj_s[j + 64]; z2 = fmaxf(z2, NEG_SLOPE * z2);
            float z3 = fi + fj_s[j + 96]; z3 = fmaxf(z3, NEG_SLOPE * z3);
            if (a0 != 0.0f) s += __expf(z0 - m);
            if (a1 != 0.0f) s += __expf(z1 - m);
            if (a2 != 0.0f) s += __expf(z2 - m);
            if (a3 != 0.0f) s += __expf(z3 - m);
        }
#pragma unroll
        for (int off = 16; off > 0; off >>= 1)
            s += __shfl_xor_sync(0xffffffffu, s, off);

        if (lane == 0) {
            m_s[r] = m;
            sinv_s[r] = (s > 0.0f) ? (1.0f / s) : 0.0f;  // empty row -> alpha all 0 (nan_to_num)
        }
    }
    __syncthreads();

    // ---- Pass 2: j-tiles of 64: load h tile, compute+store alpha, accumulate out ----
    int rg = tid >> 4;            // 0..15 -> rows rg*4 .. rg*4+3
    int dg = (tid & 15) * 4;      // dims dg .. dg+3

    unsigned long long acc[4][2];
#pragma unroll
    for (int ri = 0; ri < 4; ri++) { acc[ri][0] = 0ULL; acc[ri][1] = 0ULL; }

    const float4* hg_base = (const float4*)(g_h + (size_t)b * NN * OUT_DIM);

#pragma unroll 1
    for (int j0 = 0; j0 < NN; j0 += 64) {
        __syncthreads();  // protect h_s / alpha_t from previous tile's readers

        // load h tile [64 x 64] (1024 float4)
        {
            const float4* hg = hg_base + (size_t)j0 * (OUT_DIM / 4);
            float4* hs = (float4*)h_s;
#pragma unroll
            for (int i = 0; i < 4; i++) hs[tid + i * 256] = hg[tid + i * 256];
        }

        // alpha: warp w handles rows w*8..w*8+7, lanes over j (2 each)
#pragma unroll
        for (int rr = 0; rr < 8; rr++) {
            int r = w * 8 + rr;
            float m  = m_s[r];
            float si = sinv_s[r];
            float fi = fi_s[r];
            const float* adjrow = adj + (size_t)(i0 + r) * NN + j0;
            float* aout = alpha_out + ((size_t)(b * NN) + i0 + r) * NN + j0;
#pragma unroll
            for (int k = 0; k < 2; k++) {
                int jj = lane + 32 * k;
                float av = adjrow[jj];
                float z = fi + fj_s[j0 + jj];
                z = fmaxf(z, NEG_SLOPE * z);
                float al = 0.0f;
                if (av != 0.0f) al = __expf(z - m) * si;
                aout[jj] = al;                       // coalesced 128B store
                alpha_t[jj * 65 + r] = al;           // (jj + r) % 32 -> conflict-free
            }
        }
        __syncthreads();

        // accumulate: out[r][d] += alpha[r][jj] * h[jj][d], f32x2 packed
#pragma unroll 2
        for (int jj = 0; jj < 64; jj++) {
            const unsigned long long* hp =
                (const unsigned long long*)&h_s[jj * OUT_DIM + dg];
            unsigned long long h0 = hp[0];
            unsigned long long h1 = hp[1];
            const float* ap = &alpha_t[jj * 65 + rg * 4];
#pragma unroll
            for (int ri = 0; ri < 4; ri++) {
                float av = ap[ri];                   // broadcast within 16-thread group
                unsigned long long a2 = pack2(av, av);
                ffma2(acc[ri][0], a2, h0);
                ffma2(acc[ri][1], a2, h1);
            }
        }
    }

    // write out
#pragma unroll
    for (int ri = 0; ri < 4; ri++) {
        float o0, o1, o2, o3;
        unpack2(acc[ri][0], o0, o1);
        unpack2(acc[ri][1], o2, o3);
        size_t oidx = ((size_t)(b * NN) + i0 + rg * 4 + ri) * OUT_DIM + dg;
        *(float4*)&out[oidx] = make_float4(o0, o1, o2, o3);
    }
}

// ============================================================================
extern "C" void kernel_launch(void* const* d_in, const int* in_sizes, int n_in,
                              void* d_out, int out_size)
{
    (void)in_sizes; (void)n_in; (void)out_size;
    const float* x   = (const float*)d_in[0];   // (8, 2048, 128)
    const float* adj = (const float*)d_in[1];   // (2048, 2048)
    const float* W   = (const float*)d_in[2];   // (128, 64)
    const float* a   = (const float*)d_in[3];   // (128,)

    float* out   = (float*)d_out;                              // (8, 2048, 64)
    float* alpha = out + (size_t)BATCH * NN * OUT_DIM;         // (8, 2048, 2048)

    gat_h_kernel<<<(BATCH * NN) / 32, 256>>>(x, W, a);

    dim3 grid(NN / 64, BATCH);
    gat_main_kernel<<<grid, 256>>>(adj, out, alpha);
}